// round 11
// baseline (speedup 1.0000x reference)
#include <cuda_runtime.h>
#include <cuda_bf16.h>
#include <cuda_fp16.h>
#include <math.h>
#include <stdint.h>

#define N_NODES 100000
#define N_EDGES 800000
#define D_DATA  100
#define H_DIM   256
#define N_CLS   47
#define K_STEPS 10
#define D_VEC   25          // D_DATA / 4 float4s per row
#define ROW_BYTES 400

// ---------------- static device scratch ----------------
__device__ float g_buf0[(size_t)N_NODES * D_DATA];   // 40 MB
__device__ float g_buf1[(size_t)N_NODES * D_DATA];   // 40 MB
__device__ float g_xn[(size_t)N_NODES * D_DATA];     // 40 MB  (norm * x, persistent)
__device__ int   d_cnt[N_NODES];
__device__ int2  d_ptr2[N_NODES];                    // (begin, end)
__device__ int   d_cursor[N_NODES];
__device__ float d_norm[N_NODES];
__device__ float d_n2[N_NODES];
__device__ int   d_csr[N_EDGES];                     // BYTE offsets: src*400

// ---------------- CSR build ----------------
// d_cnt is zero at entry of every call (zero-init at load; fill_kernel re-zeros).
__global__ void count_kernel(const int* __restrict__ dst) {
    int e = blockIdx.x * blockDim.x + threadIdx.x;
    if (e < N_EDGES) atomicAdd(&d_cnt[dst[e]], 1);
}

#define SCAN_T 1024
#define SCAN_CH 98
__global__ void scan_kernel() {
    __shared__ int part[SCAN_T];
    int t = threadIdx.x;
    int beg = t * SCAN_CH;
    int end = beg + SCAN_CH; if (end > N_NODES) end = N_NODES;
    if (beg > N_NODES) beg = N_NODES;
    int s = 0;
    for (int i = beg; i < end; i++) s += d_cnt[i];
    part[t] = s;
    __syncthreads();
    for (int off = 1; off < SCAN_T; off <<= 1) {
        int v = (t >= off) ? part[t - off] : 0;
        __syncthreads();
        part[t] += v;
        __syncthreads();
    }
    int run = part[t] - s;
    for (int i = beg; i < end; i++) {
        int c = d_cnt[i];
        d_ptr2[i] = make_int2(run, run + c);
        d_cursor[i] = run;
        run += c;
        float nm = rsqrtf(fmaxf((float)c, 1.0f));
        d_norm[i] = nm;
        d_n2[i] = nm * nm;
    }
}

// scatter BYTE offsets into CSR; zero d_cnt; init xn = norm * x
#define FILL_THREADS_TOTAL (3125 * 256)   // == N_EDGES
__global__ void fill_kernel(const int* __restrict__ src, const int* __restrict__ dst,
                            const float4* __restrict__ x) {
    int e = blockIdx.x * blockDim.x + threadIdx.x;
    if (e < N_EDGES) {
        int d = dst[e];
        int p = atomicAdd(&d_cursor[d], 1);
        d_csr[p] = src[e] * ROW_BYTES;
    }
    if (e < N_NODES) d_cnt[e] = 0;
    for (int i = e; i < N_NODES * D_VEC; i += FILL_THREADS_TOTAL) {
        int node = i / D_VEC;
        float nm = d_norm[node];
        float4 v = __ldcs(&x[i]);
        v.x *= nm; v.y *= nm; v.z *= nm; v.w *= nm;
        ((float4*)g_xn)[i] = v;
    }
}

// ---------------- propagation ----------------
// Uniform step: gout = s1 * sum_e gin[src] + 0.1 * term
//   t < K-1: s1 = 0.9*n2[i], term = xn  (g-space)
//   t = K-1: s1 = 0.9*norm[i], term = x (h output)
__global__ void prop_kernel(const char* __restrict__ gin_bytes,
                            float4* __restrict__ gout,
                            const float4* __restrict__ term,
                            int last) {
    int warp = (blockIdx.x * blockDim.x + threadIdx.x) >> 5;
    int lane = threadIdx.x & 31;
    if (warp >= N_NODES) return;
    int2 pe = __ldg(&d_ptr2[warp]);
    int beg = pe.x, end = pe.y;

    const char* gbl = gin_bytes + lane * 16;   // per-lane base
    float a0 = 0.f, a1 = 0.f, a2 = 0.f, a3 = 0.f;
    bool act = lane < D_VEC;

    for (int base = beg; base < end; base += 32) {
        int n = end - base; if (n > 32) n = 32;
        int off = (lane < n) ? __ldg(&d_csr[base + lane]) : 0;   // byte offset
        #pragma unroll 4
        for (int e = 0; e < n; e++) {
            int o = __shfl_sync(0xffffffffu, off, e);
            if (act) {
                float4 v = *(const float4*)(gbl + o);
                a0 += v.x; a1 += v.y; a2 += v.z; a3 += v.w;
            }
        }
    }

    float s1 = 0.9f * (last ? d_norm[warp] : d_n2[warp]);

    if (act) {
        float4 tv = __ldcs(&term[warp * D_VEC + lane]);
        float4 o;
        o.x = s1 * a0 + 0.1f * tv.x;
        o.y = s1 * a1 + 0.1f * tv.y;
        o.z = s1 * a2 + 0.1f * tv.z;
        o.w = s1 * a3 + 0.1f * tv.w;
        if (last) __stcs(&gout[warp * D_VEC + lane], o);
        else      gout[warp * D_VEC + lane] = o;
    }
}

// ---------------- MLP via warp-level mma.sync (fp16 in, fp32 accum) ----------
// (unchanged from best-measured R10 version)
#define TILE_M 128
#define MLP_THREADS 512
#define HS_W   60
#define W1T_W  60
#define ZS_W   132
#define W2T_W  132

#define OFF_HS   0
#define OFF_W1T  30720
#define OFF_ZS   92160
#define OFF_W2T  159744
#define OFF_B1   185088
#define OFF_B2   186112
#define MLP_SMEM_BYTES 186304

__device__ __forceinline__ void mma16816(float& c0, float& c1, float& c2, float& c3,
                                         uint32_t a0, uint32_t a1, uint32_t a2, uint32_t a3,
                                         uint32_t b0, uint32_t b1) {
    asm volatile(
        "mma.sync.aligned.m16n8k16.row.col.f32.f16.f16.f32 "
        "{%0,%1,%2,%3}, {%4,%5,%6,%7}, {%8,%9}, {%0,%1,%2,%3};"
        : "+f"(c0), "+f"(c1), "+f"(c2), "+f"(c3)
        : "r"(a0), "r"(a1), "r"(a2), "r"(a3), "r"(b0), "r"(b1));
}

__device__ __forceinline__ uint32_t pack_h2(float lo, float hi) {
    __half2 h = __floats2half2_rn(lo, hi);
    return *(uint32_t*)&h;
}

__global__ void __launch_bounds__(MLP_THREADS, 1)
mlp_mma_kernel(const float* __restrict__ h,
               const float* __restrict__ W1, const float* __restrict__ b1,
               const float* __restrict__ W2, const float* __restrict__ b2,
               float* __restrict__ out) {
    extern __shared__ char smc[];
    uint32_t* hsW  = (uint32_t*)(smc + OFF_HS);
    uint32_t* w1W  = (uint32_t*)(smc + OFF_W1T);
    uint32_t* zsW  = (uint32_t*)(smc + OFF_ZS);
    uint32_t* w2W  = (uint32_t*)(smc + OFF_W2T);
    float*    b1s  = (float*)(smc + OFF_B1);
    float*    b2s  = (float*)(smc + OFF_B2);

    int tid = threadIdx.x;
    int wid = tid >> 5, lane = tid & 31;
    int gr = lane >> 2, tc = lane & 3;
    int wp = wid >> 1, half = wid & 1;
    int m0 = wp * 16;

    for (int i = tid; i < 256 * W1T_W; i += MLP_THREADS) {
        int j = i / W1T_W, kw = i % W1T_W;
        int k = kw * 2;
        float lo = (k     < D_DATA) ? W1[k * H_DIM + j]       : 0.f;
        float hi = (k + 1 < D_DATA) ? W1[(k + 1) * H_DIM + j] : 0.f;
        w1W[i] = pack_h2(lo, hi);
    }
    for (int i = tid; i < 48 * W2T_W; i += MLP_THREADS) {
        int c = i / W2T_W, jw = i % W2T_W;
        int j = jw * 2;
        float lo = (c < N_CLS && j     < H_DIM) ? W2[j * N_CLS + c]       : 0.f;
        float hi = (c < N_CLS && j + 1 < H_DIM) ? W2[(j + 1) * N_CLS + c] : 0.f;
        w2W[i] = pack_h2(lo, hi);
    }
    for (int i = tid; i < H_DIM; i += MLP_THREADS) b1s[i] = b1[i];
    if (tid < 48) b2s[tid] = (tid < N_CLS) ? b2[tid] : 0.f;
    __syncthreads();

    int n_tiles = (N_NODES + TILE_M - 1) / TILE_M;   // 782
    for (int tile = blockIdx.x; tile < n_tiles; tile += gridDim.x) {
        int node0 = tile * TILE_M;

        for (int i = tid; i < TILE_M * HS_W; i += MLP_THREADS) {
            int m = i / HS_W, kw = i % HS_W;
            int k = kw * 2;
            int node = node0 + m;
            uint32_t v = 0;
            if (node < N_NODES && k < D_DATA) {
                float2 f = *(const float2*)(h + (size_t)node * D_DATA + k);
                v = pack_h2(f.x, f.y);
            }
            hsW[i] = v;
        }
        __syncthreads();

        #pragma unroll 1
        for (int chh = 0; chh < 2; chh++) {
            int n0 = (half * 2 + chh) * 64;
            float acc[8][4];
            #pragma unroll
            for (int nb = 0; nb < 8; nb++)
                #pragma unroll
                for (int q = 0; q < 4; q++) acc[nb][q] = 0.f;

            #pragma unroll
            for (int kb = 0; kb < 7; kb++) {
                int kwb = kb * 8 + tc;
                uint32_t a0 = hsW[(m0 + gr) * HS_W + kwb];
                uint32_t a1 = hsW[(m0 + gr + 8) * HS_W + kwb];
                uint32_t a2 = hsW[(m0 + gr) * HS_W + kwb + 4];
                uint32_t a3 = hsW[(m0 + gr + 8) * HS_W + kwb + 4];
                #pragma unroll
                for (int nb = 0; nb < 8; nb++) {
                    int j = n0 + nb * 8 + gr;
                    uint32_t b0 = w1W[j * W1T_W + kwb];
                    uint32_t b1f = w1W[j * W1T_W + kwb + 4];
                    mma16816(acc[nb][0], acc[nb][1], acc[nb][2], acc[nb][3],
                             a0, a1, a2, a3, b0, b1f);
                }
            }
            #pragma unroll
            for (int nb = 0; nb < 8; nb++) {
                int j = n0 + nb * 8 + 2 * tc;
                float2 bb = *(const float2*)(b1s + j);
                float f0 = fmaxf(acc[nb][0] + bb.x, 0.f);
                float f1 = fmaxf(acc[nb][1] + bb.y, 0.f);
                float f2 = fmaxf(acc[nb][2] + bb.x, 0.f);
                float f3 = fmaxf(acc[nb][3] + bb.y, 0.f);
                int jw = (n0 + nb * 8) / 2 + tc;
                zsW[(m0 + gr) * ZS_W + jw]     = pack_h2(f0, f1);
                zsW[(m0 + gr + 8) * ZS_W + jw] = pack_h2(f2, f3);
            }
        }
        __syncthreads();

        {
            float acc[3][4];
            #pragma unroll
            for (int nb = 0; nb < 3; nb++)
                #pragma unroll
                for (int q = 0; q < 4; q++) acc[nb][q] = 0.f;

            #pragma unroll 4
            for (int kb = 0; kb < 16; kb++) {
                int kwb = kb * 8 + tc;
                uint32_t a0 = zsW[(m0 + gr) * ZS_W + kwb];
                uint32_t a1 = zsW[(m0 + gr + 8) * ZS_W + kwb];
                uint32_t a2 = zsW[(m0 + gr) * ZS_W + kwb + 4];
                uint32_t a3 = zsW[(m0 + gr + 8) * ZS_W + kwb + 4];
                #pragma unroll
                for (int nb = 0; nb < 3; nb++) {
                    int c = (half * 3 + nb) * 8 + gr;
                    uint32_t b0 = w2W[c * W2T_W + kwb];
                    uint32_t b1f = w2W[c * W2T_W + kwb + 4];
                    mma16816(acc[nb][0], acc[nb][1], acc[nb][2], acc[nb][3],
                             a0, a1, a2, a3, b0, b1f);
                }
            }

            int nodeA = node0 + m0 + gr;
            int nodeB = nodeA + 8;
            #pragma unroll
            for (int nb = 0; nb < 3; nb++) {
                int c = (half * 3 + nb) * 8 + 2 * tc;
                if (c < N_CLS) {
                    float bc = b2s[c];
                    if (nodeA < N_NODES) out[(size_t)nodeA * N_CLS + c] = acc[nb][0] + bc;
                    if (nodeB < N_NODES) out[(size_t)nodeB * N_CLS + c] = acc[nb][2] + bc;
                }
                if (c + 1 < N_CLS) {
                    float bc = b2s[c + 1];
                    if (nodeA < N_NODES) out[(size_t)nodeA * N_CLS + c + 1] = acc[nb][1] + bc;
                    if (nodeB < N_NODES) out[(size_t)nodeB * N_CLS + c + 1] = acc[nb][3] + bc;
                }
            }
        }
        __syncthreads();
    }
}

// ---------------- launch ----------------
extern "C" void kernel_launch(void* const* d_in, const int* in_sizes, int n_in,
                              void* d_out, int out_size) {
    const float* x   = (const float*)d_in[0];
    const int*   src = (const int*)d_in[1];
    const int*   dst = (const int*)d_in[2];
    const float* W1  = (const float*)d_in[3];
    const float* b1  = (const float*)d_in[4];
    const float* W2  = (const float*)d_in[5];
    const float* b2  = (const float*)d_in[6];
    float* out = (float*)d_out;

    cudaFuncSetAttribute(mlp_mma_kernel, cudaFuncAttributeMaxDynamicSharedMemorySize,
                         MLP_SMEM_BYTES);

    float* p0 = nullptr;
    float* p1 = nullptr;
    float* pxn = nullptr;
    cudaGetSymbolAddress((void**)&p0, g_buf0);
    cudaGetSymbolAddress((void**)&p1, g_buf1);
    cudaGetSymbolAddress((void**)&pxn, g_xn);

    int nb_edges = (N_EDGES + 255) / 256;       // 3125
    int nb_prop = (N_NODES * 32 + 63) / 64;     // 64-thread blocks, warp per node

    count_kernel<<<nb_edges, 256>>>(dst);                           // launch 0
    scan_kernel<<<1, SCAN_T>>>();                                   // launch 1
    fill_kernel<<<nb_edges, 256>>>(src, dst, (const float4*)x);     // launch 2 (+init xn)

    // t = 0: xn -> buf0                                             // launch 3 (profiled)
    prop_kernel<<<nb_prop, 64>>>((const char*)pxn, (float4*)p0,
                                 (const float4*)pxn, 0);
    // t = 1..9: ping-pong buf0 <-> buf1; teleport term = xn (or x for last)
    for (int t = 1; t < K_STEPS; t++) {
        const float* gin = (t & 1) ? p0 : p1;
        float* gout      = (t & 1) ? p1 : p0;
        int last = (t == K_STEPS - 1);
        prop_kernel<<<nb_prop, 64>>>((const char*)gin, (float4*)gout,
                                     last ? (const float4*)x : (const float4*)pxn,
                                     last);
    }
    // t=9 (odd) wrote p1 -> h lives in g_buf1
    mlp_mma_kernel<<<148, MLP_THREADS, MLP_SMEM_BYTES>>>(p1, W1, b1, W2, b2, out);
}